// round 8
// baseline (speedup 1.0000x reference)
#include <cuda_runtime.h>
#include <cuda_bf16.h>
#include <math.h>
#include <stdint.h>

#define Bsz 2
#define Nn  1024
#define Dd  512
#define Hh  16
#define DHd 32

// Scratch (device globals; no allocation allowed)
__device__ float g_y[Bsz*Nn*Dd];         // pre-LN residual

// split-precision bf16 operands
__device__ __nv_bfloat16 g_xhi[Bsz*Nn*Dd],   g_xlo[Bsz*Nn*Dd];     // x
__device__ __nv_bfloat16 g_whi[1536*Dd],     g_wlo[1536*Dd];       // att_w
__device__ __nv_bfloat16 g_fwhi[Dd*Dd],      g_fwlo[Dd*Dd];        // ff_w
__device__ __nv_bfloat16 g_atthi[Bsz*Nn*Dd], g_attlo[Bsz*Nn*Dd];   // attn out
// Q/K/V in bf16 hi/lo, [B,H,N,32]; Q pre-scaled by 1/sqrt(32)
__device__ __nv_bfloat16 g_qhi[Bsz*Hh*Nn*DHd], g_qlo[Bsz*Hh*Nn*DHd];
__device__ __nv_bfloat16 g_khi[Bsz*Hh*Nn*DHd], g_klo[Bsz*Hh*Nn*DHd];
__device__ __nv_bfloat16 g_vhi[Bsz*Hh*Nn*DHd], g_vlo[Bsz*Hh*Nn*DHd];

// ===================== warp-MMA helpers ====================================
__device__ __forceinline__ uint32_t smem_u32(const void* p) {
    uint32_t a;
    asm("{ .reg .u64 t; cvta.to.shared.u64 t, %1; cvt.u32.u64 %0, t; }"
        : "=r"(a) : "l"(p));
    return a;
}
__device__ __forceinline__ void ldsm_x4(uint32_t* r, uint32_t addr) {
    asm volatile("ldmatrix.sync.aligned.m8n8.x4.shared.b16 {%0,%1,%2,%3}, [%4];"
        : "=r"(r[0]), "=r"(r[1]), "=r"(r[2]), "=r"(r[3]) : "r"(addr));
}
__device__ __forceinline__ void ldsm_x4_t(uint32_t* r, uint32_t addr) {
    asm volatile("ldmatrix.sync.aligned.m8n8.x4.trans.shared.b16 {%0,%1,%2,%3}, [%4];"
        : "=r"(r[0]), "=r"(r[1]), "=r"(r[2]), "=r"(r[3]) : "r"(addr));
}
__device__ __forceinline__ void mma_16816(float* c, const uint32_t* a, const uint32_t* b) {
    asm volatile("mma.sync.aligned.m16n8k16.row.col.f32.bf16.bf16.f32 "
        "{%0,%1,%2,%3}, {%4,%5,%6,%7}, {%8,%9}, {%0,%1,%2,%3};"
        : "+f"(c[0]), "+f"(c[1]), "+f"(c[2]), "+f"(c[3])
        : "r"(a[0]), "r"(a[1]), "r"(a[2]), "r"(a[3]), "r"(b[0]), "r"(b[1]));
}
__device__ __forceinline__ uint32_t bfpack(__nv_bfloat16 a, __nv_bfloat16 b) {
    return (uint32_t)__bfloat16_as_ushort(a) | ((uint32_t)__bfloat16_as_ushort(b) << 16);
}
__device__ __forceinline__ void split2(float x0, float x1, uint32_t& uh, uint32_t& ul) {
    __nv_bfloat16 h0 = __float2bfloat16(x0), h1 = __float2bfloat16(x1);
    __nv_bfloat16 l0 = __float2bfloat16(x0 - __bfloat162float(h0));
    __nv_bfloat16 l1 = __float2bfloat16(x1 - __bfloat162float(h1));
    uh = bfpack(h0, h1); ul = bfpack(l0, l1);
}
__device__ __forceinline__ void split4(float x0, float x1, float x2, float x3,
                                       uint2& uh, uint2& ul) {
    split2(x0, x1, uh.x, ul.x);
    split2(x2, x3, uh.y, ul.y);
}

// ---------------------------------------------------------------------------
// Kernel 0: fp32 -> bf16 hi/lo split
// ---------------------------------------------------------------------------
__global__ __launch_bounds__(256) void split_kernel(
    const float* __restrict__ src, __nv_bfloat16* __restrict__ hi,
    __nv_bfloat16* __restrict__ lo, int n4)
{
    int idx = blockIdx.x * 256 + threadIdx.x;
    if (idx >= n4) return;
    float4 v = ((const float4*)src)[idx];
    uint2 uh, ul;
    split4(v.x, v.y, v.z, v.w, uh, ul);
    *(uint2*)&hi[(size_t)idx*4] = uh;
    *(uint2*)&lo[(size_t)idx*4] = ul;
}

// ---------------------------------------------------------------------------
// Templated MMA mainloop (proven in R5/R6).
// ---------------------------------------------------------------------------
template<int MFR>
__device__ __forceinline__ void mma_mainloop(
    const __nv_bfloat16* __restrict__ gAhi, const __nv_bfloat16* __restrict__ gAlo,
    const __nv_bfloat16* __restrict__ gBhi, const __nv_bfloat16* __restrict__ gBlo,
    int m0, int o0, char* smem, float (&acc)[MFR][4][4])
{
    constexpr int MT = MFR * 32;
    constexpr int S_AHI = 0;
    constexpr int S_ALO = MT * 64;
    constexpr int S_BHI = 2 * MT * 64;
    constexpr int S_BLO = 2 * MT * 64 + 8192;
    const int tid = threadIdx.x;
    const int warp = tid >> 5, lane = tid & 31;
    const int wm = warp >> 2, wn = warp & 3;
    const uint32_t sb = smem_u32(smem);

    uint4 rAh[MFR/2], rAl[MFR/2], rBh[2], rBl[2];

    #define LOAD_CHUNK(kc) do { \
        _Pragma("unroll") \
        for (int i = 0; i < MFR/2; i++) { \
            int u = tid + i*256; \
            int row = u >> 2, c8 = (u & 3) * 8; \
            size_t g = (size_t)(m0 + row)*512 + (kc)*32 + c8; \
            rAh[i] = *(const uint4*)&gAhi[g]; \
            rAl[i] = *(const uint4*)&gAlo[g]; \
        } \
        _Pragma("unroll") \
        for (int i = 0; i < 2; i++) { \
            int u = tid + i*256; \
            int row = u >> 2, c8 = (u & 3) * 8; \
            size_t g = (size_t)(o0 + row)*512 + (kc)*32 + c8; \
            rBh[i] = *(const uint4*)&gBhi[g]; \
            rBl[i] = *(const uint4*)&gBlo[g]; \
        } \
    } while (0)

    #define STORE_CHUNK() do { \
        _Pragma("unroll") \
        for (int i = 0; i < MFR/2; i++) { \
            int u = tid + i*256; \
            int row = u >> 2, q = u & 3; \
            uint32_t off = row*64 + ((q ^ ((row>>1)&3)) << 4); \
            *(uint4*)(smem + S_AHI + off) = rAh[i]; \
            *(uint4*)(smem + S_ALO + off) = rAl[i]; \
        } \
        _Pragma("unroll") \
        for (int i = 0; i < 2; i++) { \
            int u = tid + i*256; \
            int row = u >> 2, q = u & 3; \
            uint32_t off = row*64 + ((q ^ ((row>>1)&3)) << 4); \
            *(uint4*)(smem + S_BHI + off) = rBh[i]; \
            *(uint4*)(smem + S_BLO + off) = rBl[i]; \
        } \
    } while (0)

    LOAD_CHUNK(0);
    STORE_CHUNK();
    __syncthreads();

    for (int kc = 0; kc < 16; kc++) {
        if (kc < 15) LOAD_CHUNK(kc + 1);
        #pragma unroll
        for (int ks = 0; ks < 2; ks++) {
            uint32_t bh[4][2], bl[4][2];
            #pragma unroll
            for (int p = 0; p < 2; p++) {
                int nrow = wn*32 + p*16 + (lane & 7) + ((lane >> 4) << 3);
                int qb = ks*2 + ((lane >> 3) & 1);
                uint32_t off = nrow*64 + ((qb ^ ((nrow>>1)&3)) << 4);
                uint32_t r[4];
                ldsm_x4(r, sb + S_BHI + off);
                bh[2*p][0] = r[0]; bh[2*p][1] = r[1];
                bh[2*p+1][0] = r[2]; bh[2*p+1][1] = r[3];
                ldsm_x4(r, sb + S_BLO + off);
                bl[2*p][0] = r[0]; bl[2*p][1] = r[1];
                bl[2*p+1][0] = r[2]; bl[2*p+1][1] = r[3];
            }
            #pragma unroll
            for (int mf = 0; mf < MFR; mf++) {
                int arow = wm*(MFR*16) + mf*16 + (lane & 15);
                int qb = ks*2 + (lane >> 4);
                uint32_t off = arow*64 + ((qb ^ ((arow>>1)&3)) << 4);
                uint32_t ah[4], al[4];
                ldsm_x4(ah, sb + S_AHI + off);
                ldsm_x4(al, sb + S_ALO + off);
                #pragma unroll
                for (int nf = 0; nf < 4; nf++) {
                    mma_16816(acc[mf][nf], ah, bh[nf]);
                    mma_16816(acc[mf][nf], ah, bl[nf]);
                    mma_16816(acc[mf][nf], al, bh[nf]);
                }
            }
        }
        __syncthreads();
        if (kc < 15) { STORE_CHUNK(); __syncthreads(); }
    }
    #undef LOAD_CHUNK
    #undef STORE_CHUNK
}

// ---------------------------------------------------------------------------
// Kernel 1: QKV GEMM. CTA 64x128, grid (12, 32). Epilogue writes split bf16
// Q (pre-scaled), K, V in [B,H,N,32].
// ---------------------------------------------------------------------------
__global__ __launch_bounds__(256) void gemm_qkv_mma()
{
    extern __shared__ __align__(16) char smem[];
    const int m0 = blockIdx.y * 64, o0 = blockIdx.x * 128;
    float acc[2][4][4] = {};
    mma_mainloop<2>(g_xhi, g_xlo, g_whi, g_wlo, m0, o0, smem, acc);

    const float SCALE = 0.17677669529663689f;  // 1/sqrt(32)
    const int tid = threadIdx.x, warp = tid >> 5, lane = tid & 31;
    const int wm = warp >> 2, wn = warp & 3;
    const int bb = m0 >> 10;
    #pragma unroll
    for (int mf = 0; mf < 2; mf++) {
        int r0 = (m0 & 1023) + wm*32 + mf*16 + (lane >> 2);
        #pragma unroll
        for (int nf = 0; nf < 4; nf++) {
            int o = o0 + wn*32 + nf*8 + (lane & 3)*2;
            int which = o >> 9, h = (o >> 5) & 15, d = o & 31;
            __nv_bfloat16 *dhi, *dlo;
            float scl = 1.0f;
            if (which == 0)      { dhi = g_qhi; dlo = g_qlo; scl = SCALE; }
            else if (which == 1) { dhi = g_khi; dlo = g_klo; }
            else                 { dhi = g_vhi; dlo = g_vlo; }
            size_t e0 = ((size_t)(bb*Hh + h)*Nn + r0)*DHd + d;
            size_t e1 = e0 + 8*DHd;
            uint32_t uh, ul;
            split2(acc[mf][nf][0]*scl, acc[mf][nf][1]*scl, uh, ul);
            *(uint32_t*)&dhi[e0] = uh; *(uint32_t*)&dlo[e0] = ul;
            split2(acc[mf][nf][2]*scl, acc[mf][nf][3]*scl, uh, ul);
            *(uint32_t*)&dhi[e1] = uh; *(uint32_t*)&dlo[e1] = ul;
        }
    }
}

// ---------------------------------------------------------------------------
// Kernel 2: Tensor-core attention, 2 heads per CTA, bias direct from global
// (L1 catches the cross-head reuse; no SMEM staging, no extra syncs).
// Block = 64 queries x 2 heads (hp, hp+8), 256 thr = 8 warps
// (warp w: head hh = w>>2, query subtile wq = w&3).
// ---------------------------------------------------------------------------
#define S_QH   0              // 2 heads * 4096
#define S_QL   8192
#define S_KH   16384
#define S_KL   24576
#define S_VH   32768
#define S_VL   40960
#define S_MASK 49152
#define ATTN_SMEM (49152 + 256)

__global__ __launch_bounds__(256) void attn_mma(
    const float* __restrict__ pdist, const float* __restrict__ angle,
    const float* __restrict__ adj,   const unsigned char* __restrict__ mask,
    const float* __restrict__ gamma_p, const float* __restrict__ gamma_adj,
    const float* __restrict__ w_bias)
{
    extern __shared__ __align__(16) char smem[];
    const int b = blockIdx.z, hp = blockIdx.y;
    const int i0 = blockIdx.x * 64;
    const int t = threadIdx.x, w = t >> 5, lane = t & 31;
    const int hh = w >> 2;           // which of the 2 heads this warp serves
    const int wq = w & 3;            // query subtile
    const int h = hp + 8*hh;

    const uint32_t sb = smem_u32(smem);
    uint32_t* smask = (uint32_t*)(smem + S_MASK);

    const size_t ho0 = (size_t)(b*Hh + hp)*Nn*DHd;
    const size_t ho1 = (size_t)(b*Hh + hp + 8)*Nn*DHd;

    // ---- Stage Q (both heads), extract fragments ----
    {
        const int th = t & 127, hh2 = t >> 7;
        const size_t hof = hh2 ? ho1 : ho0;
        #pragma unroll
        for (int u0 = 0; u0 < 2; u0++) {
            int u = th + u0*128;
            int row = u >> 2, q = u & 3;
            uint32_t off = hh2*4096 + row*64 + ((uint32_t)(q ^ ((row>>1)&3)) << 4);
            size_t g = hof + (size_t)(i0 + row)*DHd + q*8;
            *(uint4*)(smem + S_QH + off) = *(const uint4*)&g_qhi[g];
            *(uint4*)(smem + S_QL + off) = *(const uint4*)&g_qlo[g];
        }
    }
    __syncthreads();

    uint32_t qh[2][4], ql[2][4];
    #pragma unroll
    for (int ks = 0; ks < 2; ks++) {
        int arow = wq*16 + (lane & 15);
        int qb = ks*2 + (lane >> 4);
        uint32_t off = hh*4096 + arow*64 + ((uint32_t)(qb ^ ((arow>>1)&3)) << 4);
        ldsm_x4(qh[ks], sb + S_QH + off);
        ldsm_x4(ql[ks], sb + S_QL + off);
    }

    const float gp  = gamma_p[h];
    const float ga  = gamma_adj[h];
    const float wb0 = w_bias[h*2+0];
    const float wb1 = w_bias[h*2+1];
    const unsigned char* mk = mask + b*Nn;

    const int qrow = wq*16 + (lane >> 2);
    const size_t bi = ((size_t)b*Nn + i0 + qrow)*Nn;
    const float* pd0 = pdist + bi;   const float* pd1 = pd0 + 8*Nn;
    const float* aj0 = adj + bi;     const float* aj1 = aj0 + 8*Nn;
    const float* an0 = angle + bi*2; const float* an1 = an0 + 16*Nn;

    float o[4][4] = {};
    float l0 = 0.f, l1 = 0.f;

    for (int jt = 0; jt < 16; jt++) {
        const int j0 = jt*64;
        __syncthreads();
        // ---- cooperative K/V load (2 heads) + mask ----
        #pragma unroll
        for (int u0 = 0; u0 < 2; u0++) {
            int u = t + u0*256;              // 0..511
            int hh2 = u >> 8;
            int rr = (u >> 2) & 63;
            int qq = u & 3;
            uint32_t off = hh2*4096 + rr*64 + ((uint32_t)(qq ^ ((rr>>1)&3)) << 4);
            size_t g = (hh2 ? ho1 : ho0) + (size_t)(j0 + rr)*DHd + qq*8;
            *(uint4*)(smem + S_KH + off) = *(const uint4*)&g_khi[g];
            *(uint4*)(smem + S_KL + off) = *(const uint4*)&g_klo[g];
            *(uint4*)(smem + S_VH + off) = *(const uint4*)&g_vhi[g];
            *(uint4*)(smem + S_VL + off) = *(const uint4*)&g_vlo[g];
        }
        if (t < 16) smask[t] = ((const uint32_t*)(mk + j0))[t];
        __syncthreads();

        const uint32_t hb = hh*4096;
        #pragma unroll
        for (int kc = 0; kc < 4; kc++) {
            // ---- K fragments ----
            uint32_t kh[2][2][2], kl[2][2][2];
            #pragma unroll
            for (int ks = 0; ks < 2; ks++) {
                int nrow = kc*16 + (lane & 7) + ((lane >> 4) << 3);
                int qb = ks*2 + ((lane >> 3) & 1);
                uint32_t off = hb + nrow*64 + ((uint32_t)(qb ^ ((nrow>>1)&3)) << 4);
                uint32_t r[4];
                ldsm_x4(r, sb + S_KH + off);
                kh[ks][0][0] = r[0]; kh[ks][0][1] = r[1];
                kh[ks][1][0] = r[2]; kh[ks][1][1] = r[3];
                ldsm_x4(r, sb + S_KL + off);
                kl[ks][0][0] = r[0]; kl[ks][0][1] = r[1];
                kl[ks][1][0] = r[2]; kl[ks][1][1] = r[3];
            }
            // ---- QK^T ----
            float c[2][4] = {};
            #pragma unroll
            for (int nt2 = 0; nt2 < 2; nt2++)
                #pragma unroll
                for (int ks = 0; ks < 2; ks++) {
                    mma_16816(c[nt2], qh[ks], kh[ks][nt2]);
                    mma_16816(c[nt2], qh[ks], kl[ks][nt2]);
                    mma_16816(c[nt2], ql[ks], kh[ks][nt2]);
                }
            // ---- bias (direct global; L1-shared across the 2 head groups) ----
            uint32_t ah[4], al[4];
            #pragma unroll
            for (int nt2 = 0; nt2 < 2; nt2++) {
                int jl = (kc*2 + nt2)*8 + (lane & 3)*2;
                int j = j0 + jl;
                float2 p0 = *(const float2*)(pd0 + j);
                float2 p1 = *(const float2*)(pd1 + j);
                float2 a0 = *(const float2*)(aj0 + j);
                float2 a1 = *(const float2*)(aj1 + j);
                float4 g0 = *(const float4*)(an0 + 2*j);
                float4 g1 = *(const float4*)(an1 + 2*j);
                float s0 = c[nt2][0] - gp*p0.x + wb0*g0.x + wb1*g0.y + ga*a0.x;
                float s1 = c[nt2][1] - gp*p0.y + wb0*g0.z + wb1*g0.w + ga*a0.y;
                float s2 = c[nt2][2] - gp*p1.x + wb0*g1.x + wb1*g1.y + ga*a1.x;
                float s3 = c[nt2][3] - gp*p1.y + wb0*g1.z + wb1*g1.w + ga*a1.y;
                float e0 = __expf(s0), e1 = __expf(s1);
                float e2 = __expf(s2), e3 = __expf(s3);
                const unsigned char* mb = (const unsigned char*)smask;
                if (mb[jl])     { e0 = 0.f; e2 = 0.f; }
                if (mb[jl + 1]) { e1 = 0.f; e3 = 0.f; }
                l0 += e0 + e1; l1 += e2 + e3;
                split2(e0, e1, ah[nt2*2 + 0], al[nt2*2 + 0]);
                split2(e2, e3, ah[nt2*2 + 1], al[nt2*2 + 1]);
            }
            // ---- V fragments (trans) + PV ----
            uint32_t vh[4][2], vl[4][2];
            #pragma unroll
            for (int nh = 0; nh < 2; nh++) {
                int vrow = kc*16 + (lane & 15);
                int qv = nh*2 + (lane >> 4);
                uint32_t off = hb + vrow*64 + ((uint32_t)(qv ^ ((vrow>>1)&3)) << 4);
                uint32_t r[4];
                ldsm_x4_t(r, sb + S_VH + off);
                vh[nh*2+0][0] = r[0]; vh[nh*2+0][1] = r[1];
                vh[nh*2+1][0] = r[2]; vh[nh*2+1][1] = r[3];
                ldsm_x4_t(r, sb + S_VL + off);
                vl[nh*2+0][0] = r[0]; vl[nh*2+0][1] = r[1];
                vl[nh*2+1][0] = r[2]; vl[nh*2+1][1] = r[3];
            }
            #pragma unroll
            for (int nv = 0; nv < 4; nv++) {
                mma_16816(o[nv], ah, vh[nv]);
                mma_16816(o[nv], al, vh[nv]);
                mma_16816(o[nv], ah, vl[nv]);
            }
        }
    }

    // normalize
    l0 += __shfl_xor_sync(0xffffffffu, l0, 1);
    l0 += __shfl_xor_sync(0xffffffffu, l0, 2);
    l1 += __shfl_xor_sync(0xffffffffu, l1, 1);
    l1 += __shfl_xor_sync(0xffffffffu, l1, 2);
    const float inv0 = 1.0f / l0, inv1 = 1.0f / l1;

    const int i_r = i0 + qrow;
    #pragma unroll
    for (int nv = 0; nv < 4; nv++) {
        int dh = nv*8 + (lane & 3)*2;
        size_t e0 = ((size_t)b*Nn + i_r)*Dd + h*DHd + dh;
        size_t e1 = e0 + 8*Dd;
        uint32_t uh, ul;
        split2(o[nv][0]*inv0, o[nv][1]*inv0, uh, ul);
        *(uint32_t*)&g_atthi[e0] = uh; *(uint32_t*)&g_attlo[e0] = ul;
        split2(o[nv][2]*inv1, o[nv][3]*inv1, uh, ul);
        *(uint32_t*)&g_atthi[e1] = uh; *(uint32_t*)&g_attlo[e1] = ul;
    }
}

// ---------------------------------------------------------------------------
// Kernel 3: FF GEMM + residual + bias.
// ---------------------------------------------------------------------------
__global__ __launch_bounds__(256) void gemm_ff_mma(
    const float* __restrict__ xres, const float* __restrict__ ffb)
{
    extern __shared__ __align__(16) char smem[];
    const int m0 = blockIdx.y * 64, o0 = blockIdx.x * 128;
    float acc[2][4][4] = {};
    mma_mainloop<2>(g_atthi, g_attlo, g_fwhi, g_fwlo, m0, o0, smem, acc);

    const int tid = threadIdx.x, warp = tid >> 5, lane = tid & 31;
    const int wm = warp >> 2, wn = warp & 3;
    #pragma unroll
    for (int mf = 0; mf < 2; mf++) {
        int r0 = m0 + wm*32 + mf*16 + (lane >> 2);
        #pragma unroll
        for (int nf = 0; nf < 4; nf++) {
            int o = o0 + wn*32 + nf*8 + (lane & 3)*2;
            float2 fb = *(const float2*)&ffb[o];
            float2 x0 = *(const float2*)&xres[(size_t)r0*512 + o];
            float2 x1 = *(const float2*)&xres[(size_t)(r0+8)*512 + o];
            *(float2*)&g_y[(size_t)r0*512 + o] = make_float2(
                acc[mf][nf][0] + x0.x + fb.x, acc[mf][nf][1] + x0.y + fb.y);
            *(float2*)&g_y[(size_t)(r0+8)*512 + o] = make_float2(
                acc[mf][nf][2] + x1.x + fb.x, acc[mf][nf][3] + x1.y + fb.y);
        }
    }
}

// ---------------------------------------------------------------------------
// Kernel 4: LayerNorm rows of g_y -> out.
// ---------------------------------------------------------------------------
__global__ __launch_bounds__(128) void ln_kernel(
    const float* __restrict__ lnw, const float* __restrict__ lnb,
    float* __restrict__ out)
{
    const int row = blockIdx.x;
    const int t = threadIdx.x;
    const float4 v = ((const float4*)&g_y[(size_t)row*512])[t];

    float s  = v.x + v.y + v.z + v.w;
    float ss = v.x*v.x + v.y*v.y + v.z*v.z + v.w*v.w;

    __shared__ float rs[4], rss[4];
    #pragma unroll
    for (int off = 16; off > 0; off >>= 1) {
        s  += __shfl_down_sync(0xffffffffu, s,  off);
        ss += __shfl_down_sync(0xffffffffu, ss, off);
    }
    if ((t & 31) == 0) { rs[t >> 5] = s; rss[t >> 5] = ss; }
    __syncthreads();
    float sum  = rs[0]  + rs[1]  + rs[2]  + rs[3];
    float sums = rss[0] + rss[1] + rss[2] + rss[3];

    const float mu   = sum  * (1.0f/512.0f);
    const float var  = sums * (1.0f/512.0f) - mu*mu;
    const float rstd = rsqrtf(var + 1e-5f);

    const float4 w = ((const float4*)lnw)[t];
    const float4 b = ((const float4*)lnb)[t];
    float4 o;
    o.x = (v.x - mu)*rstd*w.x + b.x;
    o.y = (v.y - mu)*rstd*w.y + b.y;
    o.z = (v.z - mu)*rstd*w.z + b.z;
    o.w = (v.w - mu)*rstd*w.w + b.w;
    ((float4*)&out[(size_t)row*512])[t] = o;
}

// ---------------------------------------------------------------------------
extern "C" void kernel_launch(void* const* d_in, const int* in_sizes, int n_in,
                              void* d_out, int out_size)
{
    const float* x         = (const float*)d_in[0];
    const float* pdist     = (const float*)d_in[1];
    const float* angle     = (const float*)d_in[2];
    const float* adj       = (const float*)d_in[3];
    const unsigned char* mask = (const unsigned char*)d_in[4];
    const float* gamma_p   = (const float*)d_in[5];
    const float* gamma_adj = (const float*)d_in[6];
    const float* w_bias    = (const float*)d_in[7];
    const float* att_w     = (const float*)d_in[8];
    const float* ff_w      = (const float*)d_in[9];
    const float* ff_b      = (const float*)d_in[10];
    const float* ln_w      = (const float*)d_in[11];
    const float* ln_b      = (const float*)d_in[12];
    float* out = (float*)d_out;

    __nv_bfloat16 *xhi, *xlo, *whi, *wlo, *fwhi, *fwlo;
    cudaGetSymbolAddress((void**)&xhi,  g_xhi);
    cudaGetSymbolAddress((void**)&xlo,  g_xlo);
    cudaGetSymbolAddress((void**)&whi,  g_whi);
    cudaGetSymbolAddress((void**)&wlo,  g_wlo);
    cudaGetSymbolAddress((void**)&fwhi, g_fwhi);
    cudaGetSymbolAddress((void**)&fwlo, g_fwlo);

    static bool attr_set = false;
    if (!attr_set) {
        cudaFuncSetAttribute(attn_mma,
            cudaFuncAttributeMaxDynamicSharedMemorySize, ATTN_SMEM);
        attr_set = true;
    }

    split_kernel<<<(Bsz*Nn*Dd/4 + 255)/256, 256>>>(x,     xhi,  xlo,  Bsz*Nn*Dd/4);
    split_kernel<<<(1536*Dd/4  + 255)/256, 256>>>(att_w, whi,  wlo,  1536*Dd/4);
    split_kernel<<<(Dd*Dd/4    + 255)/256, 256>>>(ff_w,  fwhi, fwlo, Dd*Dd/4);

    gemm_qkv_mma<<<dim3(1536/128, 2048/64), 256, 24576>>>();
    attn_mma<<<dim3(Nn/64, Hh/2, Bsz), 256, ATTN_SMEM>>>(
        pdist, angle, adj, mask, gamma_p, gamma_adj, w_bias);
    gemm_ff_mma<<<dim3(512/128, 2048/64), 256, 24576>>>(x, ff_b);
    ln_kernel<<<Bsz*Nn, 128>>>(ln_w, ln_b, out);
}

// round 9
// speedup vs baseline: 1.4503x; 1.4503x over previous
#include <cuda_runtime.h>
#include <cuda_bf16.h>
#include <math.h>
#include <stdint.h>

#define Bsz 2
#define Nn  1024
#define Dd  512
#define Hh  16
#define DHd 32

// Scratch (device globals; no allocation allowed)
__device__ float g_y[Bsz*Nn*Dd];         // pre-LN residual

// split-precision bf16 operands
__device__ __nv_bfloat16 g_xhi[Bsz*Nn*Dd],   g_xlo[Bsz*Nn*Dd];     // x
__device__ __nv_bfloat16 g_whi[1536*Dd],     g_wlo[1536*Dd];       // att_w
__device__ __nv_bfloat16 g_fwhi[Dd*Dd],      g_fwlo[Dd*Dd];        // ff_w
__device__ __nv_bfloat16 g_atthi[Bsz*Nn*Dd], g_attlo[Bsz*Nn*Dd];   // attn out
// Q/K/V in bf16 hi/lo, [B,H,N,32]; Q pre-scaled by 1/sqrt(32)
__device__ __nv_bfloat16 g_qhi[Bsz*Hh*Nn*DHd], g_qlo[Bsz*Hh*Nn*DHd];
__device__ __nv_bfloat16 g_khi[Bsz*Hh*Nn*DHd], g_klo[Bsz*Hh*Nn*DHd];
__device__ __nv_bfloat16 g_vhi[Bsz*Hh*Nn*DHd], g_vlo[Bsz*Hh*Nn*DHd];

// ===================== warp-MMA helpers ====================================
__device__ __forceinline__ uint32_t smem_u32(const void* p) {
    uint32_t a;
    asm("{ .reg .u64 t; cvta.to.shared.u64 t, %1; cvt.u32.u64 %0, t; }"
        : "=r"(a) : "l"(p));
    return a;
}
__device__ __forceinline__ void ldsm_x4(uint32_t* r, uint32_t addr) {
    asm volatile("ldmatrix.sync.aligned.m8n8.x4.shared.b16 {%0,%1,%2,%3}, [%4];"
        : "=r"(r[0]), "=r"(r[1]), "=r"(r[2]), "=r"(r[3]) : "r"(addr));
}
__device__ __forceinline__ void ldsm_x4_t(uint32_t* r, uint32_t addr) {
    asm volatile("ldmatrix.sync.aligned.m8n8.x4.trans.shared.b16 {%0,%1,%2,%3}, [%4];"
        : "=r"(r[0]), "=r"(r[1]), "=r"(r[2]), "=r"(r[3]) : "r"(addr));
}
__device__ __forceinline__ void mma_16816(float* c, const uint32_t* a, const uint32_t* b) {
    asm volatile("mma.sync.aligned.m16n8k16.row.col.f32.bf16.bf16.f32 "
        "{%0,%1,%2,%3}, {%4,%5,%6,%7}, {%8,%9}, {%0,%1,%2,%3};"
        : "+f"(c[0]), "+f"(c[1]), "+f"(c[2]), "+f"(c[3])
        : "r"(a[0]), "r"(a[1]), "r"(a[2]), "r"(a[3]), "r"(b[0]), "r"(b[1]));
}
__device__ __forceinline__ void cp_async16(uint32_t saddr, const void* gaddr) {
    asm volatile("cp.async.cg.shared.global [%0], [%1], 16;"
                 :: "r"(saddr), "l"(gaddr) : "memory");
}
__device__ __forceinline__ uint32_t bfpack(__nv_bfloat16 a, __nv_bfloat16 b) {
    return (uint32_t)__bfloat16_as_ushort(a) | ((uint32_t)__bfloat16_as_ushort(b) << 16);
}
__device__ __forceinline__ void split2(float x0, float x1, uint32_t& uh, uint32_t& ul) {
    __nv_bfloat16 h0 = __float2bfloat16(x0), h1 = __float2bfloat16(x1);
    __nv_bfloat16 l0 = __float2bfloat16(x0 - __bfloat162float(h0));
    __nv_bfloat16 l1 = __float2bfloat16(x1 - __bfloat162float(h1));
    uh = bfpack(h0, h1); ul = bfpack(l0, l1);
}
__device__ __forceinline__ void split4(float x0, float x1, float x2, float x3,
                                       uint2& uh, uint2& ul) {
    split2(x0, x1, uh.x, ul.x);
    split2(x2, x3, uh.y, ul.y);
}

// ---------------------------------------------------------------------------
// Kernel 0: fused fp32 -> bf16 hi/lo split for x, att_w, ff_w (one launch)
// ---------------------------------------------------------------------------
#define SPLIT_N1 (Bsz*Nn*Dd/4)
#define SPLIT_N2 (1536*Dd/4)
#define SPLIT_N3 (Dd*Dd/4)
#define SPLIT_TOT (SPLIT_N1 + SPLIT_N2 + SPLIT_N3)

__global__ __launch_bounds__(256) void split_all(
    const float* __restrict__ x, const float* __restrict__ w,
    const float* __restrict__ fw,
    __nv_bfloat16* __restrict__ xhi, __nv_bfloat16* __restrict__ xlo,
    __nv_bfloat16* __restrict__ whi, __nv_bfloat16* __restrict__ wlo,
    __nv_bfloat16* __restrict__ fwhi, __nv_bfloat16* __restrict__ fwlo)
{
    int idx = blockIdx.x * 256 + threadIdx.x;
    const float* src; __nv_bfloat16 *hi, *lo; int i;
    if (idx < SPLIT_N1)                 { src = x;  hi = xhi;  lo = xlo;  i = idx; }
    else if (idx < SPLIT_N1 + SPLIT_N2) { src = w;  hi = whi;  lo = wlo;  i = idx - SPLIT_N1; }
    else if (idx < SPLIT_TOT)           { src = fw; hi = fwhi; lo = fwlo; i = idx - SPLIT_N1 - SPLIT_N2; }
    else return;
    float4 v = ((const float4*)src)[i];
    uint2 uh, ul;
    split4(v.x, v.y, v.z, v.w, uh, ul);
    *(uint2*)&hi[(size_t)i*4] = uh;
    *(uint2*)&lo[(size_t)i*4] = ul;
}

// ---------------------------------------------------------------------------
// cp.async double-buffered MMA mainloop.
// acc[MFR][4][4] += A[m0:,:512] * B[o0:,:512]^T, hi/lo split 3-MMA.
// CTA tile (MFR*32) x 128, 256 thr, 8 warps (2m x 4n). 2-stage SMEM pipeline.
// ---------------------------------------------------------------------------
template<int MFR>
__device__ __forceinline__ void mma_mainloop(
    const __nv_bfloat16* __restrict__ gAhi, const __nv_bfloat16* __restrict__ gAlo,
    const __nv_bfloat16* __restrict__ gBhi, const __nv_bfloat16* __restrict__ gBlo,
    int m0, int o0, char* smem, float (&acc)[MFR][4][4])
{
    constexpr int MT = MFR * 32;
    constexpr int S_ALO = MT * 64;
    constexpr int S_BHI = 2 * MT * 64;
    constexpr int S_BLO = 2 * MT * 64 + 8192;
    constexpr int STAGE = 2 * MT * 64 + 16384;
    const int tid = threadIdx.x;
    const int warp = tid >> 5, lane = tid & 31;
    const int wm = warp >> 2, wn = warp & 3;
    const uint32_t sb = smem_u32(smem);

    #define ISSUE_CHUNK(kc, st) do { \
        uint32_t s0 = sb + (st) * STAGE; \
        _Pragma("unroll") \
        for (int i = 0; i < MFR/2; i++) { \
            int u = tid + i*256; \
            int row = u >> 2, q = u & 3; \
            uint32_t off = row*64 + ((uint32_t)(q ^ ((row>>1)&3)) << 4); \
            size_t g = (size_t)(m0 + row)*512 + (kc)*32 + q*8; \
            cp_async16(s0 + off,         &gAhi[g]); \
            cp_async16(s0 + S_ALO + off, &gAlo[g]); \
        } \
        _Pragma("unroll") \
        for (int i = 0; i < 2; i++) { \
            int u = tid + i*256; \
            int row = u >> 2, q = u & 3; \
            uint32_t off = row*64 + ((uint32_t)(q ^ ((row>>1)&3)) << 4); \
            size_t g = (size_t)(o0 + row)*512 + (kc)*32 + q*8; \
            cp_async16(s0 + S_BHI + off, &gBhi[g]); \
            cp_async16(s0 + S_BLO + off, &gBlo[g]); \
        } \
        asm volatile("cp.async.commit_group;" ::: "memory"); \
    } while (0)

    ISSUE_CHUNK(0, 0);
    ISSUE_CHUNK(1, 1);

    for (int kc = 0; kc < 16; kc++) {
        if (kc < 15) asm volatile("cp.async.wait_group 1;" ::: "memory");
        else         asm volatile("cp.async.wait_group 0;" ::: "memory");
        __syncthreads();
        const uint32_t s0 = sb + (uint32_t)(kc & 1) * STAGE;
        #pragma unroll
        for (int ks = 0; ks < 2; ks++) {
            uint32_t bh[4][2], bl[4][2];
            #pragma unroll
            for (int p = 0; p < 2; p++) {
                int nrow = wn*32 + p*16 + (lane & 7) + ((lane >> 4) << 3);
                int qb = ks*2 + ((lane >> 3) & 1);
                uint32_t off = nrow*64 + ((uint32_t)(qb ^ ((nrow>>1)&3)) << 4);
                uint32_t r[4];
                ldsm_x4(r, s0 + S_BHI + off);
                bh[2*p][0] = r[0]; bh[2*p][1] = r[1];
                bh[2*p+1][0] = r[2]; bh[2*p+1][1] = r[3];
                ldsm_x4(r, s0 + S_BLO + off);
                bl[2*p][0] = r[0]; bl[2*p][1] = r[1];
                bl[2*p+1][0] = r[2]; bl[2*p+1][1] = r[3];
            }
            #pragma unroll
            for (int mf = 0; mf < MFR; mf++) {
                int arow = wm*(MFR*16) + mf*16 + (lane & 15);
                int qb = ks*2 + (lane >> 4);
                uint32_t off = arow*64 + ((uint32_t)(qb ^ ((arow>>1)&3)) << 4);
                uint32_t ah[4], al[4];
                ldsm_x4(ah, s0 + off);
                ldsm_x4(al, s0 + S_ALO + off);
                #pragma unroll
                for (int nf = 0; nf < 4; nf++) {
                    mma_16816(acc[mf][nf], ah, bh[nf]);
                    mma_16816(acc[mf][nf], ah, bl[nf]);
                    mma_16816(acc[mf][nf], al, bh[nf]);
                }
            }
        }
        __syncthreads();
        if (kc + 2 < 16) ISSUE_CHUNK(kc + 2, kc & 1);
    }
    #undef ISSUE_CHUNK
}

#define GEMM_SMEM (2 * (2*64*64 + 16384))   // MFR=2: 49152 bytes (2 stages)

// ---------------------------------------------------------------------------
// Kernel 1: QKV GEMM. CTA 64x128, grid (12, 32). Epilogue writes split bf16
// Q (pre-scaled), K, V in [B,H,N,32].
// ---------------------------------------------------------------------------
__global__ __launch_bounds__(256) void gemm_qkv_mma()
{
    extern __shared__ __align__(16) char smem[];
    const int m0 = blockIdx.y * 64, o0 = blockIdx.x * 128;
    float acc[2][4][4] = {};
    mma_mainloop<2>(g_xhi, g_xlo, g_whi, g_wlo, m0, o0, smem, acc);

    const float SCALE = 0.17677669529663689f;  // 1/sqrt(32)
    const int tid = threadIdx.x, warp = tid >> 5, lane = tid & 31;
    const int wm = warp >> 2, wn = warp & 3;
    const int bb = m0 >> 10;
    #pragma unroll
    for (int mf = 0; mf < 2; mf++) {
        int r0 = (m0 & 1023) + wm*32 + mf*16 + (lane >> 2);
        #pragma unroll
        for (int nf = 0; nf < 4; nf++) {
            int o = o0 + wn*32 + nf*8 + (lane & 3)*2;
            int which = o >> 9, h = (o >> 5) & 15, d = o & 31;
            __nv_bfloat16 *dhi, *dlo;
            float scl = 1.0f;
            if (which == 0)      { dhi = g_qhi; dlo = g_qlo; scl = SCALE; }
            else if (which == 1) { dhi = g_khi; dlo = g_klo; }
            else                 { dhi = g_vhi; dlo = g_vlo; }
            size_t e0 = ((size_t)(bb*Hh + h)*Nn + r0)*DHd + d;
            size_t e1 = e0 + 8*DHd;
            uint32_t uh, ul;
            split2(acc[mf][nf][0]*scl, acc[mf][nf][1]*scl, uh, ul);
            *(uint32_t*)&dhi[e0] = uh; *(uint32_t*)&dlo[e0] = ul;
            split2(acc[mf][nf][2]*scl, acc[mf][nf][3]*scl, uh, ul);
            *(uint32_t*)&dhi[e1] = uh; *(uint32_t*)&dlo[e1] = ul;
        }
    }
}

// ---------------------------------------------------------------------------
// Kernel 2: Tensor-core fused attention — EXACT R6 winner structure.
// Block = 64 queries x (head,batch), 128 thr (4 warps x 16 queries).
// ---------------------------------------------------------------------------
__global__ __launch_bounds__(128) void attn_mma(
    const float* __restrict__ pdist, const float* __restrict__ angle,
    const float* __restrict__ adj,   const unsigned char* __restrict__ mask,
    const float* __restrict__ gamma_p, const float* __restrict__ gamma_adj,
    const float* __restrict__ w_bias)
{
    __shared__ __align__(16) char sQh[4096];
    __shared__ __align__(16) char sQl[4096];
    __shared__ __align__(16) char sKh[4096];
    __shared__ __align__(16) char sKl[4096];
    __shared__ __align__(16) char sVh[4096];
    __shared__ __align__(16) char sVl[4096];
    __shared__ uint32_t smask[16];

    const int b = blockIdx.z, h = blockIdx.y;
    const int i0 = blockIdx.x * 64;
    const int t = threadIdx.x, w = t >> 5, lane = t & 31;

    const size_t ho = (size_t)(b*Hh + h)*Nn*DHd;
    const __nv_bfloat16* gQh = g_qhi + ho;
    const __nv_bfloat16* gQl = g_qlo + ho;
    const __nv_bfloat16* gKh = g_khi + ho;
    const __nv_bfloat16* gKl = g_klo + ho;
    const __nv_bfloat16* gVh = g_vhi + ho;
    const __nv_bfloat16* gVl = g_vlo + ho;

    const uint32_t sbQh = smem_u32(sQh), sbQl = smem_u32(sQl);
    const uint32_t sbKh = smem_u32(sKh), sbKl = smem_u32(sKl);
    const uint32_t sbVh = smem_u32(sVh), sbVl = smem_u32(sVl);

    // Load Q tile 64x32 hi/lo into swizzled smem
    #pragma unroll
    for (int u0 = 0; u0 < 2; u0++) {
        int u = t + u0*128;
        int row = u >> 2, q = u & 3;
        uint32_t off = row*64 + ((uint32_t)(q ^ ((row>>1)&3)) << 4);
        size_t g = (size_t)(i0 + row)*DHd + q*8;
        *(uint4*)(sQh + off) = *(const uint4*)&gQh[g];
        *(uint4*)(sQl + off) = *(const uint4*)&gQl[g];
    }
    __syncthreads();

    // Q fragments (held in registers for the whole sweep)
    uint32_t qh[2][4], ql[2][4];
    #pragma unroll
    for (int ks = 0; ks < 2; ks++) {
        int arow = w*16 + (lane & 15);
        int qb = ks*2 + (lane >> 4);
        uint32_t off = arow*64 + ((uint32_t)(qb ^ ((arow>>1)&3)) << 4);
        ldsm_x4(qh[ks], sbQh + off);
        ldsm_x4(ql[ks], sbQl + off);
    }

    const float gp  = gamma_p[h];
    const float ga  = gamma_adj[h];
    const float wb0 = w_bias[h*2+0];
    const float wb1 = w_bias[h*2+1];
    const unsigned char* mk = mask + b*Nn;

    const int qrow = w*16 + (lane >> 2);
    const size_t bi = ((size_t)b*Nn + i0 + qrow)*Nn;
    const float* pd0 = pdist + bi;   const float* pd1 = pd0 + 8*Nn;
    const float* aj0 = adj + bi;     const float* aj1 = aj0 + 8*Nn;
    const float* an0 = angle + bi*2; const float* an1 = an0 + 16*Nn;

    float o[4][4] = {};
    float l0 = 0.f, l1 = 0.f;

    for (int jt = 0; jt < 16; jt++) {
        const int j0 = jt*64;
        __syncthreads();
        {   // cooperative tile load
            #pragma unroll
            for (int u0 = 0; u0 < 2; u0++) {
                int u = t + u0*128;
                int row = u >> 2, q = u & 3;
                uint32_t off = row*64 + ((uint32_t)(q ^ ((row>>1)&3)) << 4);
                size_t g = (size_t)(j0 + row)*DHd + q*8;
                *(uint4*)(sKh + off) = *(const uint4*)&gKh[g];
                *(uint4*)(sKl + off) = *(const uint4*)&gKl[g];
                *(uint4*)(sVh + off) = *(const uint4*)&gVh[g];
                *(uint4*)(sVl + off) = *(const uint4*)&gVl[g];
            }
        }
        if (t < 16) smask[t] = ((const uint32_t*)(mk + j0))[t];
        __syncthreads();

        #pragma unroll
        for (int kc = 0; kc < 4; kc++) {
            // ---- K fragments ----
            uint32_t kh[2][2][2], kl[2][2][2];
            #pragma unroll
            for (int ks = 0; ks < 2; ks++) {
                int nrow = kc*16 + (lane & 7) + ((lane >> 4) << 3);
                int qb = ks*2 + ((lane >> 3) & 1);
                uint32_t off = nrow*64 + ((uint32_t)(qb ^ ((nrow>>1)&3)) << 4);
                uint32_t r[4];
                ldsm_x4(r, sbKh + off);
                kh[ks][0][0] = r[0]; kh[ks][0][1] = r[1];
                kh[ks][1][0] = r[2]; kh[ks][1][1] = r[3];
                ldsm_x4(r, sbKl + off);
                kl[ks][0][0] = r[0]; kl[ks][0][1] = r[1];
                kl[ks][1][0] = r[2]; kl[ks][1][1] = r[3];
            }
            // ---- QK^T ----
            float c[2][4] = {};
            #pragma unroll
            for (int nt2 = 0; nt2 < 2; nt2++)
                #pragma unroll
                for (int ks = 0; ks < 2; ks++) {
                    mma_16816(c[nt2], qh[ks], kh[ks][nt2]);
                    mma_16816(c[nt2], qh[ks], kl[ks][nt2]);
                    mma_16816(c[nt2], ql[ks], kh[ks][nt2]);
                }
            // ---- bias + mask + exp, pack P hi/lo ----
            uint32_t ah[4], al[4];
            #pragma unroll
            for (int nt2 = 0; nt2 < 2; nt2++) {
                int jl = (kc*2 + nt2)*8 + (lane & 3)*2;
                int j = j0 + jl;
                float2 p0 = *(const float2*)(pd0 + j);
                float2 p1 = *(const float2*)(pd1 + j);
                float2 a0 = *(const float2*)(aj0 + j);
                float2 a1 = *(const float2*)(aj1 + j);
                float4 g0 = *(const float4*)(an0 + 2*j);
                float4 g1 = *(const float4*)(an1 + 2*j);
                float s0 = c[nt2][0] - gp*p0.x + wb0*g0.x + wb1*g0.y + ga*a0.x;
                float s1 = c[nt2][1] - gp*p0.y + wb0*g0.z + wb1*g0.w + ga*a0.y;
                float s2 = c[nt2][2] - gp*p1.x + wb0*g1.x + wb1*g1.y + ga*a1.x;
                float s3 = c[nt2][3] - gp*p1.y + wb0*g1.z + wb1*g1.w + ga*a1.y;
                float e0 = __expf(s0), e1 = __expf(s1);
                float e2 = __expf(s2), e3 = __expf(s3);
                const unsigned char* mb = (const unsigned char*)smask;
                if (mb[jl])     { e0 = 0.f; e2 = 0.f; }
                if (mb[jl + 1]) { e1 = 0.f; e3 = 0.f; }
                l0 += e0 + e1; l1 += e2 + e3;
                split2(e0, e1, ah[nt2*2 + 0], al[nt2*2 + 0]);
                split2(e2, e3, ah[nt2*2 + 1], al[nt2*2 + 1]);
            }
            // ---- V fragments (trans) + PV ----
            uint32_t vh[4][2], vl[4][2];
            #pragma unroll
            for (int nh = 0; nh < 2; nh++) {
                int vrow = kc*16 + (lane & 15);
                int qv = nh*2 + (lane >> 4);
                uint32_t off = vrow*64 + ((uint32_t)(qv ^ ((vrow>>1)&3)) << 4);
                uint32_t r[4];
                ldsm_x4_t(r, sbVh + off);
                vh[nh*2+0][0] = r[0]; vh[nh*2+0][1] = r[1];
                vh[nh*2+1][0] = r[2]; vh[nh*2+1][1] = r[3];
                ldsm_x4_t(r, sbVl + off);
                vl[nh*2+0][0] = r[0]; vl[nh*2+0][1] = r[1];
                vl[nh*2+1][0] = r[2]; vl[nh*2+1][1] = r[3];
            }
            #pragma unroll
            for (int nv = 0; nv < 4; nv++) {
                mma_16816(o[nv], ah, vh[nv]);
                mma_16816(o[nv], al, vh[nv]);
                mma_16816(o[nv], ah, vl[nv]);
            }
        }
    }

    // normalize
    l0 += __shfl_xor_sync(0xffffffffu, l0, 1);
    l0 += __shfl_xor_sync(0xffffffffu, l0, 2);
    l1 += __shfl_xor_sync(0xffffffffu, l1, 1);
    l1 += __shfl_xor_sync(0xffffffffu, l1, 2);
    const float inv0 = 1.0f / l0, inv1 = 1.0f / l1;

    const int i_r = i0 + qrow;
    #pragma unroll
    for (int nv = 0; nv < 4; nv++) {
        int dh = nv*8 + (lane & 3)*2;
        size_t e0 = ((size_t)b*Nn + i_r)*Dd + h*DHd + dh;
        size_t e1 = e0 + 8*Dd;
        uint32_t uh, ul;
        split2(o[nv][0]*inv0, o[nv][1]*inv0, uh, ul);
        *(uint32_t*)&g_atthi[e0] = uh; *(uint32_t*)&g_attlo[e0] = ul;
        split2(o[nv][2]*inv1, o[nv][3]*inv1, uh, ul);
        *(uint32_t*)&g_atthi[e1] = uh; *(uint32_t*)&g_attlo[e1] = ul;
    }
}

// ---------------------------------------------------------------------------
// Kernel 3: FF GEMM + residual + bias.
// ---------------------------------------------------------------------------
__global__ __launch_bounds__(256) void gemm_ff_mma(
    const float* __restrict__ xres, const float* __restrict__ ffb)
{
    extern __shared__ __align__(16) char smem[];
    const int m0 = blockIdx.y * 64, o0 = blockIdx.x * 128;
    float acc[2][4][4] = {};
    mma_mainloop<2>(g_atthi, g_attlo, g_fwhi, g_fwlo, m0, o0, smem, acc);

    const int tid = threadIdx.x, warp = tid >> 5, lane = tid & 31;
    const int wm = warp >> 2, wn = warp & 3;
    #pragma unroll
    for (int mf = 0; mf < 2; mf++) {
        int r0 = m0 + wm*32 + mf*16 + (lane >> 2);
        #pragma unroll
        for (int nf = 0; nf < 4; nf++) {
            int o = o0 + wn*32 + nf*8 + (lane & 3)*2;
            float2 fb = *(const float2*)&ffb[o];
            float2 x0 = *(const float2*)&xres[(size_t)r0*512 + o];
            float2 x1 = *(const float2*)&xres[(size_t)(r0+8)*512 + o];
            *(float2*)&g_y[(size_t)r0*512 + o] = make_float2(
                acc[mf][nf][0] + x0.x + fb.x, acc[mf][nf][1] + x0.y + fb.y);
            *(float2*)&g_y[(size_t)(r0+8)*512 + o] = make_float2(
                acc[mf][nf][2] + x1.x + fb.x, acc[mf][nf][3] + x1.y + fb.y);
        }
    }
}

// ---------------------------------------------------------------------------
// Kernel 4: LayerNorm rows of g_y -> out.
// ---------------------------------------------------------------------------
__global__ __launch_bounds__(128) void ln_kernel(
    const float* __restrict__ lnw, const float* __restrict__ lnb,
    float* __restrict__ out)
{
    const int row = blockIdx.x;
    const int t = threadIdx.x;
    const float4 v = ((const float4*)&g_y[(size_t)row*512])[t];

    float s  = v.x + v.y + v.z + v.w;
    float ss = v.x*v.x + v.y*v.y + v.z*v.z + v.w*v.w;

    __shared__ float rs[4], rss[4];
    #pragma unroll
    for (int off = 16; off > 0; off >>= 1) {
        s  += __shfl_down_sync(0xffffffffu, s,  off);
        ss += __shfl_down_sync(0xffffffffu, ss, off);
    }
    if ((t & 31) == 0) { rs[t >> 5] = s; rss[t >> 5] = ss; }
    __syncthreads();
    float sum  = rs[0]  + rs[1]  + rs[2]  + rs[3];
    float sums = rss[0] + rss[1] + rss[2] + rss[3];

    const float mu   = sum  * (1.0f/512.0f);
    const float var  = sums * (1.0f/512.0f) - mu*mu;
    const float rstd = rsqrtf(var + 1e-5f);

    const float4 w = ((const float4*)lnw)[t];
    const float4 b = ((const float4*)lnb)[t];
    float4 o;
    o.x = (v.x - mu)*rstd*w.x + b.x;
    o.y = (v.y - mu)*rstd*w.y + b.y;
    o.z = (v.z - mu)*rstd*w.z + b.z;
    o.w = (v.w - mu)*rstd*w.w + b.w;
    ((float4*)&out[(size_t)row*512])[t] = o;
}

// ---------------------------------------------------------------------------
extern "C" void kernel_launch(void* const* d_in, const int* in_sizes, int n_in,
                              void* d_out, int out_size)
{
    const float* x         = (const float*)d_in[0];
    const float* pdist     = (const float*)d_in[1];
    const float* angle     = (const float*)d_in[2];
    const float* adj       = (const float*)d_in[3];
    const unsigned char* mask = (const unsigned char*)d_in[4];
    const float* gamma_p   = (const float*)d_in[5];
    const float* gamma_adj = (const float*)d_in[6];
    const float* w_bias    = (const float*)d_in[7];
    const float* att_w     = (const float*)d_in[8];
    const float* ff_w      = (const float*)d_in[9];
    const float* ff_b      = (const float*)d_in[10];
    const float* ln_w      = (const float*)d_in[11];
    const float* ln_b      = (const float*)d_in[12];
    float* out = (float*)d_out;

    __nv_bfloat16 *xhi, *xlo, *whi, *wlo, *fwhi, *fwlo;
    cudaGetSymbolAddress((void**)&xhi,  g_xhi);
    cudaGetSymbolAddress((void**)&xlo,  g_xlo);
    cudaGetSymbolAddress((void**)&whi,  g_whi);
    cudaGetSymbolAddress((void**)&wlo,  g_wlo);
    cudaGetSymbolAddress((void**)&fwhi, g_fwhi);
    cudaGetSymbolAddress((void**)&fwlo, g_fwlo);

    static bool attr_set = false;
    if (!attr_set) {
        cudaFuncSetAttribute(gemm_qkv_mma,
            cudaFuncAttributeMaxDynamicSharedMemorySize, GEMM_SMEM);
        cudaFuncSetAttribute(gemm_ff_mma,
            cudaFuncAttributeMaxDynamicSharedMemorySize, GEMM_SMEM);
        attr_set = true;
    }

    split_all<<<(SPLIT_TOT + 255)/256, 256>>>(x, att_w, ff_w,
        xhi, xlo, whi, wlo, fwhi, fwlo);

    gemm_qkv_mma<<<dim3(1536/128, 2048/64), 256, GEMM_SMEM>>>();
    attn_mma<<<dim3(Nn/64, Hh, Bsz), 128>>>(pdist, angle, adj, mask,
                                            gamma_p, gamma_adj, w_bias);
    gemm_ff_mma<<<dim3(512/128, 2048/64), 256, GEMM_SMEM>>>(x, ff_b);
    ln_kernel<<<Bsz*Nn, 128>>>(ln_w, ln_b, out);
}